// round 7
// baseline (speedup 1.0000x reference)
#include <cuda_runtime.h>
#include <cuda_bf16.h>
#include <cstdint>
#include <cstddef>

#define DIM 512
#define MAXA 100000
#define KPA 160

// ---------------- scratch (static device globals; no allocation) ----------------
__device__ float g_msg [(size_t)MAXA * DIM];
__device__ float g_f32a[(size_t)MAXA * DIM];
__device__ float g_f32b[(size_t)MAXA * DIM];
__device__ float g_bias[(size_t)MAXA * DIM];
// activation planes: hi[MAXA*Kp] then lo[MAXA*Kp]
__device__ __align__(16) __nv_bfloat16 g_pa[(size_t)2 * MAXA * KPA];
__device__ __align__(16) __nv_bfloat16 g_pg[(size_t)2 * MAXA * DIM];
__device__ __align__(16) __nv_bfloat16 g_p0[(size_t)2 * MAXA * DIM];
__device__ __align__(16) __nv_bfloat16 g_p1[(size_t)2 * MAXA * DIM];
// transposed + bf16-split weight planes: hi[512][Kp] then lo[512][Kp] per GEMM
__device__ __align__(16) __nv_bfloat16 g_wt[3997696];

// ---------------- helpers ----------------
__device__ __forceinline__ uint32_t s2u(const void* p) {
    uint32_t a;
    asm("{ .reg .u64 t; cvta.to.shared.u64 t, %1; cvt.u32.u64 %0, t; }" : "=r"(a) : "l"(p));
    return a;
}

#define CP16(dst, src) \
    asm volatile("cp.async.cg.shared.global [%0], [%1], 16;" :: "r"(dst), "l"(src) : "memory")
#define CP_COMMIT() asm volatile("cp.async.commit_group;" ::: "memory")
#define CP_WAIT1()  asm volatile("cp.async.wait_group 1;" ::: "memory")

#define LDSM4(r, addr) \
    asm volatile("ldmatrix.sync.aligned.m8n8.x4.shared.b16 {%0,%1,%2,%3}, [%4];" \
        : "=r"((r)[0]), "=r"((r)[1]), "=r"((r)[2]), "=r"((r)[3]) : "r"(addr))

#define MMA16816(d, a, b0, b1) \
    asm volatile("mma.sync.aligned.m16n8k16.row.col.f32.bf16.bf16.f32 " \
        "{%0,%1,%2,%3}, {%4,%5,%6,%7}, {%8,%9}, {%0,%1,%2,%3};" \
        : "+f"((d)[0]), "+f"((d)[1]), "+f"((d)[2]), "+f"((d)[3]) \
        : "r"((a)[0]), "r"((a)[1]), "r"((a)[2]), "r"((a)[3]), "r"(b0), "r"(b1))

__device__ __forceinline__ void split2(float a0, float a1, uint32_t& h, uint32_t& l) {
    __nv_bfloat16 h0 = __float2bfloat16(a0);
    __nv_bfloat16 h1 = __float2bfloat16(a1);
    __nv_bfloat16 b0 = __float2bfloat16(a0 - __bfloat162float(h0));
    __nv_bfloat16 b1 = __float2bfloat16(a1 - __bfloat162float(h1));
    h = (uint32_t)__bfloat16_as_ushort(h0) | ((uint32_t)__bfloat16_as_ushort(h1) << 16);
    l = (uint32_t)__bfloat16_as_ushort(b0) | ((uint32_t)__bfloat16_as_ushort(b1) << 16);
}

// ---------------- weight prep: W[K,512] fp32 -> Wt hi/lo [512][Kp] bf16 ----------------
__global__ void prep_weight(const float* __restrict__ W, __nv_bfloat16* __restrict__ hi,
                            int Kreal, int Kp) {
    __nv_bfloat16* lo = hi + (size_t)512 * Kp;
    int total = 512 * Kp;
    for (int idx = blockIdx.x * blockDim.x + threadIdx.x; idx < total;
         idx += gridDim.x * blockDim.x) {
        int n = idx / Kp, k = idx - n * Kp;
        float v = (k < Kreal) ? W[(size_t)k * 512 + n] : 0.f;
        __nv_bfloat16 h = __float2bfloat16(v);
        hi[idx] = h;
        lo[idx] = __float2bfloat16(v - __bfloat162float(h));
    }
}

// ---------------- atom feature prep: f_atoms[M,133] -> planes [M,KPA] ----------------
__global__ void prep_atoms(const float* __restrict__ fa, __nv_bfloat16* __restrict__ hi, int M) {
    __nv_bfloat16* lo = hi + (size_t)MAXA * KPA;
    int total = M * KPA;
    for (int idx = blockIdx.x * blockDim.x + threadIdx.x; idx < total;
         idx += gridDim.x * blockDim.x) {
        int row = idx / KPA, k = idx - row * KPA;
        float v = (k < 133) ? fa[(size_t)row * 133 + k] : 0.f;
        __nv_bfloat16 h = __float2bfloat16(v);
        hi[idx] = h;
        lo[idx] = __float2bfloat16(v - __bfloat162float(h));
    }
}

// ---------------- HMMA GEMM: out = f(A @ W + bias + add), A pre-split bf16 planes ------
// grid (4, ceil(M/128)), 256 threads, dyn smem 81920 B, 2 CTAs/SM.
// BK=32. smem rows 80 B (64 B data + 16 pad) -> conflict-free ldmatrix.
// A double-buffered @0 (buf*20480; lo plane +10240), B @40960 likewise.
template<bool RELU_OUT, bool EMIT_PLANES>
__global__ void __launch_bounds__(256, 2) gemm_mma(
    const __nv_bfloat16* __restrict__ Ahi, size_t APL,
    const __nv_bfloat16* __restrict__ Whi,
    const float* __restrict__ bias, const float* __restrict__ addf,
    float* __restrict__ Cf, __nv_bfloat16* __restrict__ Cp,
    int M, int Kp, int zero_row0)
{
    extern __shared__ __align__(16) char smem[];
    const uint32_t sb = s2u(smem);
    const uint32_t RS = 80, APLN = 10240, BBASE = 40960, BUFS = 20480;
    const size_t PPL = (size_t)MAXA * DIM;

    const __nv_bfloat16* Alo = Ahi + APL;
    const __nv_bfloat16* Wlo = Whi + (size_t)512 * Kp;
    const int tid = threadIdx.x, lane = tid & 31, wid = tid >> 5;
    const int wm = wid >> 1, wn = wid & 1;    // warp grid 4x2, warp tile 32M x 64N
    const int row0 = blockIdx.y * 128, col0 = blockIdx.x * 128;
    const int nch = Kp >> 5;

    float acc[2][8][4];
    #pragma unroll
    for (int i = 0; i < 2; i++)
        #pragma unroll
        for (int j = 0; j < 8; j++)
            #pragma unroll
            for (int q = 0; q < 4; q++) acc[i][j][q] = 0.f;

    // loader coords: 2 threads per row, 16 elems (32 B) each per plane
    const int lr = tid >> 1, klo = (tid & 1) * 16;
    const int grow = row0 + lr;
    const uint32_t dst_off = (uint32_t)lr * RS + (uint32_t)klo * 2;

    auto issue = [&](int c, int buf) {
        if (grow < M) {
            const __nv_bfloat16* s = Ahi + (size_t)grow * Kp + c * 32 + klo;
            const __nv_bfloat16* s2 = Alo + (size_t)grow * Kp + c * 32 + klo;
            uint32_t d = sb + (uint32_t)buf * BUFS + dst_off;
            CP16(d, s);           CP16(d + 16, s + 8);
            CP16(d + APLN, s2);   CP16(d + APLN + 16, s2 + 8);
        }
        {
            const __nv_bfloat16* s = Whi + (size_t)(col0 + lr) * Kp + c * 32 + klo;
            const __nv_bfloat16* s2 = Wlo + (size_t)(col0 + lr) * Kp + c * 32 + klo;
            uint32_t d = sb + BBASE + (uint32_t)buf * BUFS + dst_off;
            CP16(d, s);           CP16(d + 16, s + 8);
            CP16(d + APLN, s2);   CP16(d + APLN + 16, s2 + 8);
        }
    };

    // ldmatrix constant offsets
    const uint32_t a_off = (uint32_t)(wm * 32 + (lane & 15)) * RS + (uint32_t)(lane >> 4) * 16;
    const uint32_t b_off = (uint32_t)(wn * 64 + (lane & 7) + ((lane >> 4) & 1) * 8) * RS
                           + (uint32_t)((lane >> 3) & 1) * 16;

    issue(0, 0);
    CP_COMMIT();

    for (int c = 0; c < nch; c++) {
        if (c + 1 < nch) issue(c + 1, (c + 1) & 1);
        CP_COMMIT();
        CP_WAIT1();
        __syncthreads();

        const uint32_t abase = sb + (uint32_t)(c & 1) * BUFS + a_off;
        const uint32_t bbase = sb + BBASE + (uint32_t)(c & 1) * BUFS + b_off;
        #pragma unroll
        for (int ks = 0; ks < 2; ks++) {
            uint32_t ah[2][4], al[2][4];
            #pragma unroll
            for (int mt = 0; mt < 2; mt++) {
                uint32_t aa = abase + mt * 16 * RS + ks * 32;
                LDSM4(ah[mt], aa);
                LDSM4(al[mt], aa + APLN);
            }
            #pragma unroll
            for (int ntp = 0; ntp < 4; ntp++) {
                uint32_t bh[4], bl[4];
                uint32_t ba = bbase + ntp * 16 * RS + ks * 32;
                LDSM4(bh, ba);
                LDSM4(bl, ba + APLN);
                #pragma unroll
                for (int h = 0; h < 2; h++) {
                    const int nt = ntp * 2 + h;
                    #pragma unroll
                    for (int mt = 0; mt < 2; mt++) {
                        MMA16816(acc[mt][nt], ah[mt], bh[2 * h], bh[2 * h + 1]);
                        MMA16816(acc[mt][nt], ah[mt], bl[2 * h], bl[2 * h + 1]);
                        MMA16816(acc[mt][nt], al[mt], bh[2 * h], bh[2 * h + 1]);
                    }
                }
            }
        }
        __syncthreads();
    }

    // ---- epilogue ----
    const int g = lane >> 2, tg = lane & 3;
    #pragma unroll
    for (int mt = 0; mt < 2; mt++) {
        #pragma unroll
        for (int nt = 0; nt < 8; nt++) {
            const int col = col0 + wn * 64 + nt * 8 + tg * 2;
            #pragma unroll
            for (int half = 0; half < 2; half++) {
                const int row = row0 + wm * 32 + mt * 16 + g + half * 8;
                if (row >= M) continue;
                float v0 = acc[mt][nt][half * 2 + 0];
                float v1 = acc[mt][nt][half * 2 + 1];
                if (bias) {
                    const float2 bv = *(const float2*)(bias + col);
                    v0 += bv.x; v1 += bv.y;
                }
                if (addf) {
                    const float2 av = *(const float2*)(addf + (size_t)row * DIM + col);
                    v0 += av.x; v1 += av.y;
                }
                if (RELU_OUT) { v0 = fmaxf(v0, 0.f); v1 = fmaxf(v1, 0.f); }
                if (zero_row0 && row == 0) { v0 = 0.f; v1 = 0.f; }
                if (EMIT_PLANES) {
                    uint32_t hp, lp;
                    split2(v0, v1, hp, lp);
                    *(uint32_t*)(Cp + (size_t)row * DIM + col) = hp;
                    *(uint32_t*)(Cp + PPL + (size_t)row * DIM + col) = lp;
                } else {
                    *(float2*)(Cf + (size_t)row * DIM + col) = make_float2(v0, v1);
                }
            }
        }
    }
}

// ---------------- gather-sum + optional relu + split to planes ----------------
template<bool RELU>
__global__ void gather_split(const float* __restrict__ src, const int* __restrict__ a2a,
                             __nv_bfloat16* __restrict__ hi)
{
    const size_t PPL = (size_t)MAXA * DIM;
    const int atom = blockIdx.x;
    const int t = threadIdx.x;                 // 128 threads x 4 floats
    const int* idx = a2a + (size_t)atom * 6;
    float4 acc = make_float4(0.f, 0.f, 0.f, 0.f);
    #pragma unroll
    for (int j = 0; j < 6; j++) {
        const float4 v = *(const float4*)(src + (size_t)idx[j] * DIM + t * 4);
        acc.x += v.x; acc.y += v.y; acc.z += v.z; acc.w += v.w;
    }
    if (RELU) {
        acc.x = fmaxf(acc.x, 0.f); acc.y = fmaxf(acc.y, 0.f);
        acc.z = fmaxf(acc.z, 0.f); acc.w = fmaxf(acc.w, 0.f);
    }
    uint32_t h0, l0, h1, l1;
    split2(acc.x, acc.y, h0, l0);
    split2(acc.z, acc.w, h1, l1);
    *(uint2*)(hi + (size_t)atom * DIM + t * 4)       = make_uint2(h0, h1);
    *(uint2*)(hi + PPL + (size_t)atom * DIM + t * 4) = make_uint2(l0, l1);
}

// ---------------- bond bias: g_bias[i,:] = relu(sum f_bonds[a2b[i]]) @ Wb + Wh0_b ------
__global__ void bond_bias_kernel(const float* __restrict__ f_bonds, const int* __restrict__ a2b,
                                 const float* __restrict__ Wb, const float* __restrict__ b0,
                                 float* __restrict__ dst)
{
    const int atom = blockIdx.x;
    const int t = threadIdx.x;
    __shared__ float bs[14];
    if (t < 14) {
        const int* idx = a2b + (size_t)atom * 6;
        float s = 0.f;
        #pragma unroll
        for (int j = 0; j < 6; j++) s += f_bonds[(size_t)idx[j] * 14 + t];
        bs[t] = fmaxf(s, 0.f);
    }
    __syncthreads();
    #pragma unroll
    for (int rr = 0; rr < 4; rr++) {
        int n = t + rr * 128;
        float acc = b0[n];
        #pragma unroll
        for (int k = 0; k < 14; k++) acc = fmaf(bs[k], Wb[k * DIM + n], acc);
        dst[(size_t)atom * DIM + n] = acc;
    }
}

// ---------------- segment sum via atomics ----------------
__global__ void segment_atomic(const float* __restrict__ x, const int* __restrict__ mol_ids,
                               float* __restrict__ out, int n_mols)
{
    const int atom = blockIdx.x;
    const int mid = mol_ids[atom];
    if (mid < 0 || mid >= n_mols) return;
    const int t = threadIdx.x;
    #pragma unroll
    for (int rr = 0; rr < 4; rr++) {
        int n = t + rr * 128;
        atomicAdd(out + (size_t)mid * DIM + n, x[(size_t)atom * DIM + n]);
    }
}

extern "C" void kernel_launch(void* const* d_in, const int* in_sizes, int n_in,
                              void* d_out, int out_size)
{
    const float* f_atoms = (const float*)d_in[0];
    const float* f_bonds = (const float*)d_in[1];
    const int*   a2a     = (const int*)d_in[2];
    const int*   a2b     = (const int*)d_in[3];
    const int*   mol_ids = (const int*)d_in[4];
    const int base = n_in - 16;
    const float* W_i_w  = (const float*)d_in[base + 0];
    const float* W_i_b  = (const float*)d_in[base + 1];
    const float* Wh0_w  = (const float*)d_in[base + 2];
    const float* Wh0_b  = (const float*)d_in[base + 3];
    const float* Wh1_w  = (const float*)d_in[base + 4];
    const float* Wh1_b  = (const float*)d_in[base + 5];
    const float* Wh2_w  = (const float*)d_in[base + 6];
    const float* Wh2_b  = (const float*)d_in[base + 7];
    const float* Wah0_w = (const float*)d_in[base + 8];
    const float* Wah0_b = (const float*)d_in[base + 9];
    const float* Wah1_w = (const float*)d_in[base + 10];
    const float* Wah1_b = (const float*)d_in[base + 11];
    const float* Wah2_w = (const float*)d_in[base + 12];
    const float* Wah2_b = (const float*)d_in[base + 13];
    const float* W_o_w  = (const float*)d_in[base + 14];
    const float* W_o_b  = (const float*)d_in[base + 15];

    const int M      = in_sizes[0] / 133;
    const int n_mols = out_size / DIM;

    float *p_msg, *p_f32a, *p_f32b, *p_bias;
    __nv_bfloat16 *p_pa, *p_pg, *p_p0, *p_p1, *p_wt;
    cudaGetSymbolAddress((void**)&p_msg,  g_msg);
    cudaGetSymbolAddress((void**)&p_f32a, g_f32a);
    cudaGetSymbolAddress((void**)&p_f32b, g_f32b);
    cudaGetSymbolAddress((void**)&p_bias, g_bias);
    cudaGetSymbolAddress((void**)&p_pa,   g_pa);
    cudaGetSymbolAddress((void**)&p_pg,   g_pg);
    cudaGetSymbolAddress((void**)&p_p0,   g_p0);
    cudaGetSymbolAddress((void**)&p_p1,   g_p1);
    cudaGetSymbolAddress((void**)&p_wt,   g_wt);

    // weight plane offsets in bf16 elements (hi plane; lo = hi + 512*Kp)
    const size_t OFF_WI   = 0;         // Kp=160: 2*512*160 = 163840
    const size_t OFF_WAH0 = 163840;    // Kp=160
    const size_t OFF_WH0  = 327680;    // Kp=512: 2*512*512 = 524288 each
    const size_t OFF_WH1  = 851968;
    const size_t OFF_WH2  = 1376256;
    const size_t OFF_WAH1 = 1900544;
    const size_t OFF_WAH2 = 2424832;
    const size_t OFF_WOT  = 2949120;
    const size_t OFF_WOB  = 3473408;

    const int SMEM_BYTES = 81920;
    cudaFuncSetAttribute(gemm_mma<true,  false>, cudaFuncAttributeMaxDynamicSharedMemorySize, SMEM_BYTES);
    cudaFuncSetAttribute(gemm_mma<true,  true >, cudaFuncAttributeMaxDynamicSharedMemorySize, SMEM_BYTES);
    cudaFuncSetAttribute(gemm_mma<false, false>, cudaFuncAttributeMaxDynamicSharedMemorySize, SMEM_BYTES);

    // ---- prep ----
    prep_weight<<<256, 256>>>(W_i_w,  p_wt + OFF_WI,   133, KPA);
    prep_weight<<<256, 256>>>(Wah0_w, p_wt + OFF_WAH0, 133, KPA);
    prep_weight<<<256, 256>>>(Wh0_w,  p_wt + OFF_WH0,  512, 512);
    prep_weight<<<256, 256>>>(Wh1_w,  p_wt + OFF_WH1,  512, 512);
    prep_weight<<<256, 256>>>(Wh2_w,  p_wt + OFF_WH2,  512, 512);
    prep_weight<<<256, 256>>>(Wah1_w, p_wt + OFF_WAH1, 512, 512);
    prep_weight<<<256, 256>>>(Wah2_w, p_wt + OFF_WAH2, 512, 512);
    prep_weight<<<256, 256>>>(W_o_w,                     p_wt + OFF_WOT, 512, 512);
    prep_weight<<<256, 256>>>(W_o_w + (size_t)DIM * DIM, p_wt + OFF_WOB, 512, 512);
    prep_atoms<<<512, 256>>>(f_atoms, p_pa, M);

    cudaMemsetAsync(d_out, 0, (size_t)out_size * sizeof(float), 0);

    bond_bias_kernel<<<M, 128>>>(f_bonds, a2b, Wh0_w + (size_t)DIM * DIM, Wh0_b, p_bias);

    const dim3 gg(4, (M + 127) / 128);
    const size_t APL_A = (size_t)MAXA * KPA;
    const size_t APL_D = (size_t)MAXA * DIM;

    // msg = relu(f_atoms @ W_i + b_i), row0 zeroed  -> fp32
    gemm_mma<true, false><<<gg, 256, SMEM_BYTES>>>(
        p_pa, APL_A, p_wt + OFF_WI, W_i_b, nullptr, p_msg, nullptr, M, KPA, 1);

    for (int d = 0; d < 4; d++) {
        gather_split<true><<<M, 128>>>(p_msg, a2a, p_pg);
        // t0p = split(relu(gath @ Wh0_atom + bond_bias))
        gemm_mma<true, true><<<gg, 256, SMEM_BYTES>>>(
            p_pg, APL_D, p_wt + OFF_WH0, nullptr, p_bias, nullptr, p_p0, M, 512, 0);
        // t1p = split(relu(t0 @ Wh1 + b1))
        gemm_mma<true, true><<<gg, 256, SMEM_BYTES>>>(
            p_p0, APL_D, p_wt + OFF_WH1, Wh1_b, nullptr, nullptr, p_p1, M, 512, 0);
        // msg = t1 @ Wh2 + b2 + msg (fp32, row0 zeroed)
        gemm_mma<false, false><<<gg, 256, SMEM_BYTES>>>(
            p_p1, APL_D, p_wt + OFF_WH2, Wh2_b, p_msg, p_msg, nullptr, M, 512, 1);
    }

    // a_message planes (NO relu)
    gather_split<false><<<M, 128>>>(p_msg, a2a, p_pg);

    // cc chain (planes throughout)
    gemm_mma<true, true><<<gg, 256, SMEM_BYTES>>>(
        p_pa, APL_A, p_wt + OFF_WAH0, Wah0_b, nullptr, nullptr, p_p0, M, KPA, 0);
    gemm_mma<true, true><<<gg, 256, SMEM_BYTES>>>(
        p_p0, APL_D, p_wt + OFF_WAH1, Wah1_b, nullptr, nullptr, p_p1, M, 512, 0);
    gemm_mma<true, true><<<gg, 256, SMEM_BYTES>>>(
        p_p1, APL_D, p_wt + OFF_WAH2, Wah2_b, nullptr, nullptr, p_p0, M, 512, 0);

    // out = relu(cc @ Wo_top + a_message @ Wo_bot + b_o)
    gemm_mma<false, false><<<gg, 256, SMEM_BYTES>>>(
        p_p0, APL_D, p_wt + OFF_WOT, W_o_b, nullptr, p_f32a, nullptr, M, 512, 0);
    gemm_mma<true, false><<<gg, 256, SMEM_BYTES>>>(
        p_pg, APL_D, p_wt + OFF_WOB, nullptr, p_f32a, p_f32b, nullptr, M, 512, 0);

    segment_atomic<<<M, 128>>>(p_f32b, mol_ids, (float*)d_out, n_mols);
}

// round 8
// speedup vs baseline: 1.2130x; 1.2130x over previous
#include <cuda_runtime.h>
#include <cuda_bf16.h>
#include <cstdint>
#include <cstddef>

#define DIM 512
#define MAXA 100000
#define KPA 192

// ---------------- scratch (static device globals; no allocation) ----------------
__device__ float g_msg [(size_t)MAXA * DIM];
__device__ float g_f32a[(size_t)MAXA * DIM];
__device__ float g_f32b[(size_t)MAXA * DIM];
__device__ float g_bias[(size_t)MAXA * DIM];
// activation planes: hi[...] then lo[...]
__device__ __align__(16) __nv_bfloat16 g_pa [(size_t)2 * MAXA * KPA];
__device__ __align__(16) __nv_bfloat16 g_pg [(size_t)2 * MAXA * DIM];
__device__ __align__(16) __nv_bfloat16 g_p0 [(size_t)2 * MAXA * DIM];
__device__ __align__(16) __nv_bfloat16 g_p1 [(size_t)2 * MAXA * DIM];
__device__ __align__(16) __nv_bfloat16 g_pcc[(size_t)2 * MAXA * DIM];
// transposed + bf16-split weight planes: hi[512][Kp] then lo[512][Kp] per GEMM
__device__ __align__(16) __nv_bfloat16 g_wt[4063232];

// ---------------- helpers ----------------
__device__ __forceinline__ uint32_t s2u(const void* p) {
    uint32_t a;
    asm("{ .reg .u64 t; cvta.to.shared.u64 t, %1; cvt.u32.u64 %0, t; }" : "=r"(a) : "l"(p));
    return a;
}

#define CP16(dst, src) \
    asm volatile("cp.async.cg.shared.global [%0], [%1], 16;" :: "r"(dst), "l"(src) : "memory")
#define CP_COMMIT() asm volatile("cp.async.commit_group;" ::: "memory")
#define CP_WAIT1()  asm volatile("cp.async.wait_group 1;" ::: "memory")

#define LDSM4(r, addr) \
    asm volatile("ldmatrix.sync.aligned.m8n8.x4.shared.b16 {%0,%1,%2,%3}, [%4];" \
        : "=r"((r)[0]), "=r"((r)[1]), "=r"((r)[2]), "=r"((r)[3]) : "r"(addr))

#define MMA16816(d, a, b0, b1) \
    asm volatile("mma.sync.aligned.m16n8k16.row.col.f32.bf16.bf16.f32 " \
        "{%0,%1,%2,%3}, {%4,%5,%6,%7}, {%8,%9}, {%0,%1,%2,%3};" \
        : "+f"((d)[0]), "+f"((d)[1]), "+f"((d)[2]), "+f"((d)[3]) \
        : "r"((a)[0]), "r"((a)[1]), "r"((a)[2]), "r"((a)[3]), "r"(b0), "r"(b1))

__device__ __forceinline__ void split2(float a0, float a1, uint32_t& h, uint32_t& l) {
    __nv_bfloat16 h0 = __float2bfloat16(a0);
    __nv_bfloat16 h1 = __float2bfloat16(a1);
    __nv_bfloat16 b0 = __float2bfloat16(a0 - __bfloat162float(h0));
    __nv_bfloat16 b1 = __float2bfloat16(a1 - __bfloat162float(h1));
    h = (uint32_t)__bfloat16_as_ushort(h0) | ((uint32_t)__bfloat16_as_ushort(h1) << 16);
    l = (uint32_t)__bfloat16_as_ushort(b0) | ((uint32_t)__bfloat16_as_ushort(b1) << 16);
}

// ---------------- weight prep: W[K,512] fp32 -> Wt hi/lo [512][Kp] bf16 ----------------
__global__ void prep_weight(const float* __restrict__ W, __nv_bfloat16* __restrict__ hi,
                            int Kreal, int Kp) {
    __nv_bfloat16* lo = hi + (size_t)512 * Kp;
    int total = 512 * Kp;
    for (int idx = blockIdx.x * blockDim.x + threadIdx.x; idx < total;
         idx += gridDim.x * blockDim.x) {
        int n = idx / Kp, k = idx - n * Kp;
        float v = (k < Kreal) ? W[(size_t)k * 512 + n] : 0.f;
        __nv_bfloat16 h = __float2bfloat16(v);
        hi[idx] = h;
        lo[idx] = __float2bfloat16(v - __bfloat162float(h));
    }
}

// ---------------- atom feature prep: f_atoms[M,133] -> planes [M,KPA] ----------------
__global__ void prep_atoms(const float* __restrict__ fa, __nv_bfloat16* __restrict__ hi, int M) {
    __nv_bfloat16* lo = hi + (size_t)MAXA * KPA;
    int total = M * KPA;
    for (int idx = blockIdx.x * blockDim.x + threadIdx.x; idx < total;
         idx += gridDim.x * blockDim.x) {
        int row = idx / KPA, k = idx - row * KPA;
        float v = (k < 133) ? fa[(size_t)row * 133 + k] : 0.f;
        __nv_bfloat16 h = __float2bfloat16(v);
        hi[idx] = h;
        lo[idx] = __float2bfloat16(v - __bfloat162float(h));
    }
}

// ---------------- HMMA GEMM: out = f(A @ W + bias + add), A pre-split bf16 planes ------
// CTA tile 64M x 128N, BK=64, grid (4, ceil(M/64)), 256 threads, smem 110592 B, 2 CTAs/SM.
// Both A and B double-buffered via cp.async (1 commit/chunk, wait_group 1).
// smem: A buf b @ b*18432 (hi 9216 | lo 9216); B buf b @ 36864 + b*36864 (hi 18432 | lo 18432).
// Rows 144 B (128 data + 16 pad) -> conflict-free ldmatrix.
template<bool RELU_OUT, bool EMIT_PLANES>
__global__ void __launch_bounds__(256, 2) gemm_mma(
    const __nv_bfloat16* __restrict__ Ahi, size_t APL,
    const __nv_bfloat16* __restrict__ Whi,
    const float* __restrict__ bias, const float* __restrict__ addf,
    float* __restrict__ Cf, __nv_bfloat16* __restrict__ Cp,
    int M, int Kp, int zero_row0)
{
    extern __shared__ __align__(16) char smem[];
    const uint32_t sb = s2u(smem);
    const uint32_t RS = 144;
    const uint32_t A_PLN = 9216, A_BUFS = 18432;
    const uint32_t BBASE = 36864, B_PLN = 18432, B_BUFS = 36864;
    const size_t PPL = (size_t)MAXA * DIM;

    const __nv_bfloat16* Alo = Ahi + APL;
    const __nv_bfloat16* Wlo = Whi + (size_t)512 * Kp;
    const int tid = threadIdx.x, lane = tid & 31, wid = tid >> 5;
    const int wm = wid >> 2, wn = wid & 3;    // warp grid 2x4, warp tile 32M x 32N
    const int row0 = blockIdx.y * 64, col0 = blockIdx.x * 128;
    const int nch = Kp >> 6;

    float acc[2][4][4];
    #pragma unroll
    for (int i = 0; i < 2; i++)
        #pragma unroll
        for (int j = 0; j < 4; j++)
            #pragma unroll
            for (int q = 0; q < 4; q++) acc[i][j][q] = 0.f;

    // A loader: 4 threads/row (64 rows), 32 B per plane each
    const int alr = tid >> 2, aseg = (tid & 3) * 16;          // elem offset
    const int agrow = row0 + alr;
    const uint32_t a_dst = (uint32_t)alr * RS + (uint32_t)aseg * 2;
    // B loader: 2 threads/row (128 rows), 64 B per plane each
    const int blr = tid >> 1, bseg = (tid & 1) * 32;
    const uint32_t b_dst = (uint32_t)blr * RS + (uint32_t)bseg * 2;

    auto issue = [&](int c, int buf) {
        if (agrow < M) {
            const __nv_bfloat16* s  = Ahi + (size_t)agrow * Kp + c * 64 + aseg;
            const __nv_bfloat16* s2 = Alo + (size_t)agrow * Kp + c * 64 + aseg;
            uint32_t d = sb + (uint32_t)buf * A_BUFS + a_dst;
            CP16(d, s);            CP16(d + 16, s + 8);
            CP16(d + A_PLN, s2);   CP16(d + A_PLN + 16, s2 + 8);
        }
        {
            const __nv_bfloat16* s  = Whi + (size_t)(col0 + blr) * Kp + c * 64 + bseg;
            const __nv_bfloat16* s2 = Wlo + (size_t)(col0 + blr) * Kp + c * 64 + bseg;
            uint32_t d = sb + BBASE + (uint32_t)buf * B_BUFS + b_dst;
            CP16(d, s);            CP16(d + 16, s + 8);
            CP16(d + 32, s + 16);  CP16(d + 48, s + 24);
            CP16(d + B_PLN, s2);       CP16(d + B_PLN + 16, s2 + 8);
            CP16(d + B_PLN + 32, s2 + 16); CP16(d + B_PLN + 48, s2 + 24);
        }
    };

    // ldmatrix constant offsets
    const uint32_t a_off = (uint32_t)(wm * 32 + (lane & 15)) * RS + (uint32_t)(lane >> 4) * 16;
    const uint32_t b_off = (uint32_t)(wn * 32 + (lane & 7) + ((lane >> 4) & 1) * 8) * RS
                           + (uint32_t)((lane >> 3) & 1) * 16;

    issue(0, 0);
    CP_COMMIT();

    for (int c = 0; c < nch; c++) {
        if (c + 1 < nch) issue(c + 1, (c + 1) & 1);
        CP_COMMIT();
        CP_WAIT1();
        __syncthreads();

        const uint32_t abase = sb + (uint32_t)(c & 1) * A_BUFS + a_off;
        const uint32_t bbase = sb + BBASE + (uint32_t)(c & 1) * B_BUFS + b_off;
        #pragma unroll
        for (int ks = 0; ks < 4; ks++) {
            uint32_t ah[2][4], al[2][4];
            #pragma unroll
            for (int mt = 0; mt < 2; mt++) {
                uint32_t aa = abase + mt * 16 * RS + ks * 32;
                LDSM4(ah[mt], aa);
                LDSM4(al[mt], aa + A_PLN);
            }
            #pragma unroll
            for (int ntp = 0; ntp < 2; ntp++) {
                uint32_t bh[4], bl[4];
                uint32_t ba = bbase + ntp * 16 * RS + ks * 32;
                LDSM4(bh, ba);
                LDSM4(bl, ba + B_PLN);
                #pragma unroll
                for (int h = 0; h < 2; h++) {
                    const int nt = ntp * 2 + h;
                    #pragma unroll
                    for (int mt = 0; mt < 2; mt++) {
                        MMA16816(acc[mt][nt], ah[mt], bh[2 * h], bh[2 * h + 1]);
                        MMA16816(acc[mt][nt], ah[mt], bl[2 * h], bl[2 * h + 1]);
                        MMA16816(acc[mt][nt], al[mt], bh[2 * h], bh[2 * h + 1]);
                    }
                }
            }
        }
        __syncthreads();
    }

    // ---- epilogue ----
    const int g = lane >> 2, tg = lane & 3;
    #pragma unroll
    for (int mt = 0; mt < 2; mt++) {
        #pragma unroll
        for (int nt = 0; nt < 4; nt++) {
            const int col = col0 + wn * 32 + nt * 8 + tg * 2;
            #pragma unroll
            for (int half = 0; half < 2; half++) {
                const int row = row0 + wm * 32 + mt * 16 + g + half * 8;
                if (row >= M) continue;
                float v0 = acc[mt][nt][half * 2 + 0];
                float v1 = acc[mt][nt][half * 2 + 1];
                if (bias) {
                    const float2 bv = *(const float2*)(bias + col);
                    v0 += bv.x; v1 += bv.y;
                }
                if (addf) {
                    const float2 av = *(const float2*)(addf + (size_t)row * DIM + col);
                    v0 += av.x; v1 += av.y;
                }
                if (RELU_OUT) { v0 = fmaxf(v0, 0.f); v1 = fmaxf(v1, 0.f); }
                if (zero_row0 && row == 0) { v0 = 0.f; v1 = 0.f; }
                if (EMIT_PLANES) {
                    uint32_t hp, lp;
                    split2(v0, v1, hp, lp);
                    *(uint32_t*)(Cp + (size_t)row * DIM + col) = hp;
                    *(uint32_t*)(Cp + PPL + (size_t)row * DIM + col) = lp;
                } else {
                    *(float2*)(Cf + (size_t)row * DIM + col) = make_float2(v0, v1);
                }
            }
        }
    }
}

// ---------------- gather-sum + optional relu + split to planes ----------------
template<bool RELU>
__global__ void gather_split(const float* __restrict__ src, const int* __restrict__ a2a,
                             __nv_bfloat16* __restrict__ hi)
{
    const size_t PPL = (size_t)MAXA * DIM;
    const int atom = blockIdx.x;
    const int t = threadIdx.x;                 // 128 threads x 4 floats
    const int* idx = a2a + (size_t)atom * 6;
    float4 acc = make_float4(0.f, 0.f, 0.f, 0.f);
    #pragma unroll
    for (int j = 0; j < 6; j++) {
        const float4 v = *(const float4*)(src + (size_t)idx[j] * DIM + t * 4);
        acc.x += v.x; acc.y += v.y; acc.z += v.z; acc.w += v.w;
    }
    if (RELU) {
        acc.x = fmaxf(acc.x, 0.f); acc.y = fmaxf(acc.y, 0.f);
        acc.z = fmaxf(acc.z, 0.f); acc.w = fmaxf(acc.w, 0.f);
    }
    uint32_t h0, l0, h1, l1;
    split2(acc.x, acc.y, h0, l0);
    split2(acc.z, acc.w, h1, l1);
    *(uint2*)(hi + (size_t)atom * DIM + t * 4)       = make_uint2(h0, h1);
    *(uint2*)(hi + PPL + (size_t)atom * DIM + t * 4) = make_uint2(l0, l1);
}

// ---------------- bond bias ----------------
__global__ void bond_bias_kernel(const float* __restrict__ f_bonds, const int* __restrict__ a2b,
                                 const float* __restrict__ Wb, const float* __restrict__ b0,
                                 float* __restrict__ dst)
{
    const int atom = blockIdx.x;
    const int t = threadIdx.x;
    __shared__ float bs[14];
    if (t < 14) {
        const int* idx = a2b + (size_t)atom * 6;
        float s = 0.f;
        #pragma unroll
        for (int j = 0; j < 6; j++) s += f_bonds[(size_t)idx[j] * 14 + t];
        bs[t] = fmaxf(s, 0.f);
    }
    __syncthreads();
    #pragma unroll
    for (int rr = 0; rr < 4; rr++) {
        int n = t + rr * 128;
        float acc = b0[n];
        #pragma unroll
        for (int k = 0; k < 14; k++) acc = fmaf(bs[k], Wb[k * DIM + n], acc);
        dst[(size_t)atom * DIM + n] = acc;
    }
}

// ---------------- segment sum via atomics ----------------
__global__ void segment_atomic(const float* __restrict__ x, const int* __restrict__ mol_ids,
                               float* __restrict__ out, int n_mols)
{
    const int atom = blockIdx.x;
    const int mid = mol_ids[atom];
    if (mid < 0 || mid >= n_mols) return;
    const int t = threadIdx.x;
    #pragma unroll
    for (int rr = 0; rr < 4; rr++) {
        int n = t + rr * 128;
        atomicAdd(out + (size_t)mid * DIM + n, x[(size_t)atom * DIM + n]);
    }
}

extern "C" void kernel_launch(void* const* d_in, const int* in_sizes, int n_in,
                              void* d_out, int out_size)
{
    const float* f_atoms = (const float*)d_in[0];
    const float* f_bonds = (const float*)d_in[1];
    const int*   a2a     = (const int*)d_in[2];
    const int*   a2b     = (const int*)d_in[3];
    const int*   mol_ids = (const int*)d_in[4];
    const int base = n_in - 16;
    const float* W_i_w  = (const float*)d_in[base + 0];
    const float* W_i_b  = (const float*)d_in[base + 1];
    const float* Wh0_w  = (const float*)d_in[base + 2];
    const float* Wh0_b  = (const float*)d_in[base + 3];
    const float* Wh1_w  = (const float*)d_in[base + 4];
    const float* Wh1_b  = (const float*)d_in[base + 5];
    const float* Wh2_w  = (const float*)d_in[base + 6];
    const float* Wh2_b  = (const float*)d_in[base + 7];
    const float* Wah0_w = (const float*)d_in[base + 8];
    const float* Wah0_b = (const float*)d_in[base + 9];
    const float* Wah1_w = (const float*)d_in[base + 10];
    const float* Wah1_b = (const float*)d_in[base + 11];
    const float* Wah2_w = (const float*)d_in[base + 12];
    const float* Wah2_b = (const float*)d_in[base + 13];
    const float* W_o_w  = (const float*)d_in[base + 14];
    const float* W_o_b  = (const float*)d_in[base + 15];

    const int M      = in_sizes[0] / 133;
    const int n_mols = out_size / DIM;

    float *p_msg, *p_f32a, *p_f32b, *p_bias;
    __nv_bfloat16 *p_pa, *p_pg, *p_p0, *p_p1, *p_pcc, *p_wt;
    cudaGetSymbolAddress((void**)&p_msg,  g_msg);
    cudaGetSymbolAddress((void**)&p_f32a, g_f32a);
    cudaGetSymbolAddress((void**)&p_f32b, g_f32b);
    cudaGetSymbolAddress((void**)&p_bias, g_bias);
    cudaGetSymbolAddress((void**)&p_pa,   g_pa);
    cudaGetSymbolAddress((void**)&p_pg,   g_pg);
    cudaGetSymbolAddress((void**)&p_p0,   g_p0);
    cudaGetSymbolAddress((void**)&p_p1,   g_p1);
    cudaGetSymbolAddress((void**)&p_pcc,  g_pcc);
    cudaGetSymbolAddress((void**)&p_wt,   g_wt);

    // weight plane offsets in bf16 elements (hi plane; lo = hi + 512*Kp)
    const size_t OFF_WI   = 0;         // Kp=192: 2*512*192 = 196608
    const size_t OFF_WAH0 = 196608;    // Kp=192
    const size_t OFF_WAH1 = 393216;    // Kp=512: 2*512*512 = 524288 each
    const size_t OFF_WAH2 = 917504;
    const size_t OFF_WH0  = 1441792;
    const size_t OFF_WH1  = 1966080;
    const size_t OFF_WH2  = 2490368;
    const size_t OFF_WOT  = 3014656;
    const size_t OFF_WOB  = 3538944;

    const int SMEM_BYTES = 110592;
    cudaFuncSetAttribute(gemm_mma<true,  true >, cudaFuncAttributeMaxDynamicSharedMemorySize, SMEM_BYTES);
    cudaFuncSetAttribute(gemm_mma<true,  false>, cudaFuncAttributeMaxDynamicSharedMemorySize, SMEM_BYTES);
    cudaFuncSetAttribute(gemm_mma<false, false>, cudaFuncAttributeMaxDynamicSharedMemorySize, SMEM_BYTES);

    const dim3 gg(4, (M + 63) / 64);
    const size_t APL_A = (size_t)MAXA * KPA;
    const size_t APL_D = (size_t)MAXA * DIM;

    // ---- independent cc chain FIRST (puts a K=512 gemm at launch index 5 for ncu) ----
    prep_atoms<<<512, 256>>>(f_atoms, p_pa, M);                       // 0
    prep_weight<<<256, 256>>>(Wah0_w, p_wt + OFF_WAH0, 133, KPA);     // 1
    prep_weight<<<256, 256>>>(Wah1_w, p_wt + OFF_WAH1, 512, 512);     // 2
    prep_weight<<<256, 256>>>(Wah2_w, p_wt + OFF_WAH2, 512, 512);     // 3
    gemm_mma<true, true><<<gg, 256, SMEM_BYTES>>>(                    // 4 (K=192)
        p_pa, APL_A, p_wt + OFF_WAH0, Wah0_b, nullptr, nullptr, p_p0, M, KPA, 0);
    gemm_mma<true, true><<<gg, 256, SMEM_BYTES>>>(                    // 5 (K=512)  <- PROFILED
        p_p0, APL_D, p_wt + OFF_WAH1, Wah1_b, nullptr, nullptr, p_p1, M, 512, 0);
    gemm_mma<true, true><<<gg, 256, SMEM_BYTES>>>(                    // 6 (K=512)
        p_p1, APL_D, p_wt + OFF_WAH2, Wah2_b, nullptr, nullptr, p_pcc, M, 512, 0);

    // ---- remaining prep ----
    prep_weight<<<256, 256>>>(W_i_w,  p_wt + OFF_WI,   133, KPA);
    prep_weight<<<256, 256>>>(Wh0_w,  p_wt + OFF_WH0,  512, 512);
    prep_weight<<<256, 256>>>(Wh1_w,  p_wt + OFF_WH1,  512, 512);
    prep_weight<<<256, 256>>>(Wh2_w,  p_wt + OFF_WH2,  512, 512);
    prep_weight<<<256, 256>>>(W_o_w,                     p_wt + OFF_WOT, 512, 512);
    prep_weight<<<256, 256>>>(W_o_w + (size_t)DIM * DIM, p_wt + OFF_WOB, 512, 512);
    bond_bias_kernel<<<M, 128>>>(f_bonds, a2b, Wh0_w + (size_t)DIM * DIM, Wh0_b, p_bias);

    // msg = relu(f_atoms @ W_i + b_i), row0 zeroed -> fp32
    gemm_mma<true, false><<<gg, 256, SMEM_BYTES>>>(
        p_pa, APL_A, p_wt + OFF_WI, W_i_b, nullptr, p_msg, nullptr, M, KPA, 1);

    for (int d = 0; d < 4; d++) {
        gather_split<true><<<M, 128>>>(p_msg, a2a, p_pg);
        // t0 planes = split(relu(gath @ Wh0_atom + bond_bias_map))
        gemm_mma<true, true><<<gg, 256, SMEM_BYTES>>>(
            p_pg, APL_D, p_wt + OFF_WH0, nullptr, p_bias, nullptr, p_p0, M, 512, 0);
        // t1 planes = split(relu(t0 @ Wh1 + b1))
        gemm_mma<true, true><<<gg, 256, SMEM_BYTES>>>(
            p_p0, APL_D, p_wt + OFF_WH1, Wh1_b, nullptr, nullptr, p_p1, M, 512, 0);
        // msg = t1 @ Wh2 + b2 + msg (fp32, row0 zeroed)
        gemm_mma<false, false><<<gg, 256, SMEM_BYTES>>>(
            p_p1, APL_D, p_wt + OFF_WH2, Wh2_b, p_msg, p_msg, nullptr, M, 512, 1);
    }

    // a_message planes (NO relu)
    gather_split<false><<<M, 128>>>(p_msg, a2a, p_pg);

    cudaMemsetAsync(d_out, 0, (size_t)out_size * sizeof(float), 0);

    // out = relu(cc @ Wo_top + a_message @ Wo_bot + b_o)
    gemm_mma<false, false><<<gg, 256, SMEM_BYTES>>>(
        p_pcc, APL_D, p_wt + OFF_WOT, W_o_b, nullptr, p_f32a, nullptr, M, 512, 0);
    gemm_mma<true, false><<<gg, 256, SMEM_BYTES>>>(
        p_pg, APL_D, p_wt + OFF_WOB, nullptr, p_f32a, p_f32b, nullptr, M, 512, 0);

    segment_atomic<<<M, 128>>>(p_f32b, mol_ids, (float*)d_out, n_mols);
}